// round 2
// baseline (speedup 1.0000x reference)
#include <cuda_runtime.h>
#include <math.h>

#define BB 2
#define SS 2048
#define DD 1024
#define HH 16
#define HD 64
#define BH (BB*HH)        // 32
#define MROWS (BB*SS)     // 4096
#define PAD 65            // smem row pad (65 % 32 == 1 -> conflict-free)

// ---------------- scratch (device globals; no allocations allowed) ----------
__device__ float g_q[BH * SS * HD];     // 16 MB  [bh][s][d]
__device__ float g_k[BH * SS * HD];     // 16 MB
__device__ float g_v[BH * SS * HD];     // 16 MB
__device__ float g_ctx[MROWS * DD];     // 16 MB  [b*s][h*64+d]
__device__ float g_proj[MROWS * DD];    // 16 MB  attn_out

// ---------------- kernel 1: fused QKV projection ----------------------------
// C[m,n] = sum_k hs[m,k] * W[n,k] (+bias) (*scale for q), scattered to
// [b,h,s,d] layout. Block tile 128(M) x 64(N), 256 threads, 8x4 per thread.
__global__ void qkv_gemm(const float* __restrict__ hs,
                         const float* __restrict__ Wq, const float* __restrict__ bq,
                         const float* __restrict__ Wk, const float* __restrict__ bk,
                         const float* __restrict__ Wv, const float* __restrict__ bv)
{
    __shared__ float As[16][132];   // [TK][TM+4]
    __shared__ float Bs[16][68];    // [TK][TN+4]

    const int m0   = blockIdx.y * 128;
    const int nblk = blockIdx.x;           // 0..47 (16 n-tiles per matrix)
    const int which = nblk >> 4;           // 0=q 1=k 2=v
    const int n0   = (nblk & 15) * 64;

    const float* Wp  = (which == 0) ? Wq : (which == 1 ? Wk : Wv);
    const float* bp  = (which == 0) ? bq : (which == 1 ? bk : bv);
    float*       dst = (which == 0) ? g_q : (which == 1 ? g_k : g_v);
    const float scale = (which == 0) ? 0.125f : 1.0f;   // hd^-0.5 = 1/8

    const int tid = threadIdx.x;
    const int tx = tid & 15, ty = tid >> 4;

    float acc[8][4];
#pragma unroll
    for (int i = 0; i < 8; i++)
#pragma unroll
        for (int j = 0; j < 4; j++) acc[i][j] = 0.f;

    for (int k0 = 0; k0 < DD; k0 += 16) {
#pragma unroll
        for (int i = 0; i < 8; i++) {           // A tile: 128x16
            int idx = tid + i * 256;
            int r = idx >> 4, c = idx & 15;
            As[c][r] = hs[(size_t)(m0 + r) * DD + k0 + c];
        }
#pragma unroll
        for (int i = 0; i < 4; i++) {           // B tile: 64x16
            int idx = tid + i * 256;
            int n = idx >> 4, c = idx & 15;
            Bs[c][n] = Wp[(size_t)(n0 + n) * DD + k0 + c];
        }
        __syncthreads();
#pragma unroll
        for (int kk = 0; kk < 16; kk++) {
            float a[8], bb[4];
#pragma unroll
            for (int i = 0; i < 8; i++) a[i] = As[kk][ty + 16 * i];
#pragma unroll
            for (int j = 0; j < 4; j++) bb[j] = Bs[kk][tx + 16 * j];
#pragma unroll
            for (int i = 0; i < 8; i++)
#pragma unroll
                for (int j = 0; j < 4; j++) acc[i][j] += a[i] * bb[j];
        }
        __syncthreads();
    }

#pragma unroll
    for (int i = 0; i < 8; i++) {
        int m = m0 + ty + 16 * i;
        int b = m >> 11, s = m & 2047;
#pragma unroll
        for (int j = 0; j < 4; j++) {
            int col = n0 + tx + 16 * j;
            int h = col >> 6, d = col & 63;
            float v = (acc[i][j] + bp[col]) * scale;
            dst[(((size_t)(b * HH + h)) * SS + s) * HD + d] = v;
        }
    }
}

// ---------------- kernel 2: flash attention (fp32) ---------------------------
// One block per (q-tile of 64, bh). scores = QK^T + extra + mask, online
// softmax, O += P V. 256 threads, each owns a 4x4 micro-tile of the 64x64
// score / output tiles (rows ty+16i, cols tx+16j).
__global__ void attn_kernel(const float* __restrict__ extra,
                            const float* __restrict__ mask)
{
    extern __shared__ float sm[];
    float* Qs = sm;                  // 64*PAD
    float* Ks = Qs + 64 * PAD;
    float* Vs = Ks + 64 * PAD;
    float* Ps = Vs + 64 * PAD;

    const int bh = blockIdx.y;        // 0..31
    const int b  = bh >> 4;
    const int q0 = blockIdx.x * 64;
    const int tid = threadIdx.x;
    const int tx = tid & 15, ty = tid >> 4;

#pragma unroll
    for (int i = 0; i < 16; i++) {    // Q tile 64x64
        int idx = tid + i * 256;
        int r = idx >> 6, d = idx & 63;
        Qs[r * PAD + d] = g_q[((size_t)bh * SS + q0 + r) * HD + d];
    }
    __syncthreads();

    float m_i[4], l_i[4], o[4][4];
#pragma unroll
    for (int i = 0; i < 4; i++) {
        m_i[i] = -1e30f; l_i[i] = 0.f;
#pragma unroll
        for (int j = 0; j < 4; j++) o[i][j] = 0.f;
    }

    for (int k0 = 0; k0 < SS; k0 += 64) {
#pragma unroll
        for (int i = 0; i < 16; i++) {          // K,V tiles 64x64
            int idx = tid + i * 256;
            int r = idx >> 6, d = idx & 63;
            size_t g = ((size_t)bh * SS + k0 + r) * HD + d;
            Ks[r * PAD + d] = g_k[g];
            Vs[r * PAD + d] = g_v[g];
        }
        __syncthreads();

        float sc[4][4];
#pragma unroll
        for (int i = 0; i < 4; i++)
#pragma unroll
            for (int j = 0; j < 4; j++) sc[i][j] = 0.f;

#pragma unroll 8
        for (int d = 0; d < HD; d++) {
            float a[4], bb[4];
#pragma unroll
            for (int i = 0; i < 4; i++) a[i] = Qs[(ty + 16 * i) * PAD + d];
#pragma unroll
            for (int j = 0; j < 4; j++) bb[j] = Ks[(tx + 16 * j) * PAD + d];
#pragma unroll
            for (int i = 0; i < 4; i++)
#pragma unroll
                for (int j = 0; j < 4; j++) sc[i][j] += a[i] * bb[j];
        }

        // + extra_attn + attention_mask (mask broadcasts over heads)
#pragma unroll
        for (int i = 0; i < 4; i++) {
            int qr = q0 + ty + 16 * i;
            const float* erow = extra + ((size_t)bh * SS + qr) * SS + k0;
            const float* mrow = mask  + ((size_t)b  * SS + qr) * SS + k0;
#pragma unroll
            for (int j = 0; j < 4; j++) {
                int c = tx + 16 * j;
                sc[i][j] += erow[c] + mrow[c];
            }
        }

        // online softmax update (row groups of 16 lanes share tx dimension)
#pragma unroll
        for (int i = 0; i < 4; i++) {
            float mx = sc[i][0];
#pragma unroll
            for (int j = 1; j < 4; j++) mx = fmaxf(mx, sc[i][j]);
#pragma unroll
            for (int off = 1; off < 16; off <<= 1)
                mx = fmaxf(mx, __shfl_xor_sync(0xffffffffu, mx, off));
            float mnew = fmaxf(m_i[i], mx);
            float corr = __expf(m_i[i] - mnew);
            m_i[i] = mnew;
            float rs = 0.f;
#pragma unroll
            for (int j = 0; j < 4; j++) {
                float p = __expf(sc[i][j] - mnew);
                sc[i][j] = p;
                rs += p;
            }
#pragma unroll
            for (int off = 1; off < 16; off <<= 1)
                rs += __shfl_xor_sync(0xffffffffu, rs, off);
            l_i[i] = l_i[i] * corr + rs;
#pragma unroll
            for (int j = 0; j < 4; j++) o[i][j] *= corr;
#pragma unroll
            for (int j = 0; j < 4; j++)
                Ps[(ty + 16 * i) * PAD + tx + 16 * j] = sc[i][j];
        }
        __syncthreads();

        // O += P @ V
#pragma unroll 8
        for (int kc = 0; kc < 64; kc++) {
            float a[4], bb[4];
#pragma unroll
            for (int i = 0; i < 4; i++) a[i] = Ps[(ty + 16 * i) * PAD + kc];
#pragma unroll
            for (int j = 0; j < 4; j++) bb[j] = Vs[kc * PAD + tx + 16 * j];
#pragma unroll
            for (int i = 0; i < 4; i++)
#pragma unroll
                for (int j = 0; j < 4; j++) o[i][j] += a[i] * bb[j];
        }
        __syncthreads();
    }

    const int h = bh & 15;
#pragma unroll
    for (int i = 0; i < 4; i++) {
        int qr = q0 + ty + 16 * i;
        float inv = 1.f / l_i[i];
#pragma unroll
        for (int j = 0; j < 4; j++) {
            int d = tx + 16 * j;
            g_ctx[((size_t)(b * SS) + qr) * DD + h * HD + d] = o[i][j] * inv;
        }
    }
}

// ---------------- kernel 3: output projection -------------------------------
__global__ void proj_gemm(const float* __restrict__ Wo, const float* __restrict__ bo)
{
    __shared__ float As[16][132];
    __shared__ float Bs[16][68];

    const int m0 = blockIdx.y * 128;
    const int n0 = blockIdx.x * 64;
    const int tid = threadIdx.x;
    const int tx = tid & 15, ty = tid >> 4;

    float acc[8][4];
#pragma unroll
    for (int i = 0; i < 8; i++)
#pragma unroll
        for (int j = 0; j < 4; j++) acc[i][j] = 0.f;

    for (int k0 = 0; k0 < DD; k0 += 16) {
#pragma unroll
        for (int i = 0; i < 8; i++) {
            int idx = tid + i * 256;
            int r = idx >> 4, c = idx & 15;
            As[c][r] = g_ctx[(size_t)(m0 + r) * DD + k0 + c];
        }
#pragma unroll
        for (int i = 0; i < 4; i++) {
            int idx = tid + i * 256;
            int n = idx >> 4, c = idx & 15;
            Bs[c][n] = Wo[(size_t)(n0 + n) * DD + k0 + c];
        }
        __syncthreads();
#pragma unroll
        for (int kk = 0; kk < 16; kk++) {
            float a[8], bb[4];
#pragma unroll
            for (int i = 0; i < 8; i++) a[i] = As[kk][ty + 16 * i];
#pragma unroll
            for (int j = 0; j < 4; j++) bb[j] = Bs[kk][tx + 16 * j];
#pragma unroll
            for (int i = 0; i < 8; i++)
#pragma unroll
                for (int j = 0; j < 4; j++) acc[i][j] += a[i] * bb[j];
        }
        __syncthreads();
    }
#pragma unroll
    for (int i = 0; i < 8; i++) {
        int m = m0 + ty + 16 * i;
#pragma unroll
        for (int j = 0; j < 4; j++) {
            int col = n0 + tx + 16 * j;
            g_proj[(size_t)m * DD + col] = acc[i][j] + bo[col];
        }
    }
}

// ---------------- kernel 4: residual + LayerNorm ----------------------------
__global__ void ln_kernel(const float* __restrict__ hs,
                          const float* __restrict__ gamma,
                          const float* __restrict__ beta,
                          float* __restrict__ out)
{
    const int row = blockIdx.x;           // 0..4095
    const int tid = threadIdx.x;          // 256
    __shared__ float sh_s[8], sh_s2[8];

    float x[4];
    float s = 0.f, s2 = 0.f;
#pragma unroll
    for (int i = 0; i < 4; i++) {
        int c = tid + i * 256;
        float v = hs[(size_t)row * DD + c] + g_proj[(size_t)row * DD + c];
        x[i] = v; s += v; s2 += v * v;
    }
#pragma unroll
    for (int off = 16; off; off >>= 1) {
        s  += __shfl_xor_sync(0xffffffffu, s,  off);
        s2 += __shfl_xor_sync(0xffffffffu, s2, off);
    }
    int w = tid >> 5, ln = tid & 31;
    if (ln == 0) { sh_s[w] = s; sh_s2[w] = s2; }
    __syncthreads();
    if (w == 0) {
        s  = (ln < 8) ? sh_s[ln]  : 0.f;
        s2 = (ln < 8) ? sh_s2[ln] : 0.f;
#pragma unroll
        for (int off = 4; off; off >>= 1) {
            s  += __shfl_xor_sync(0xffffffffu, s,  off);
            s2 += __shfl_xor_sync(0xffffffffu, s2, off);
        }
        if (ln == 0) { sh_s[0] = s; sh_s2[0] = s2; }
    }
    __syncthreads();
    float mu  = sh_s[0] * (1.f / DD);
    float var = sh_s2[0] * (1.f / DD) - mu * mu;
    float inv = rsqrtf(var + 1e-5f);
#pragma unroll
    for (int i = 0; i < 4; i++) {
        int c = tid + i * 256;
        out[(size_t)row * DD + c] = (x[i] - mu) * inv * gamma[c] + beta[c];
    }
}

// ---------------- launch -----------------------------------------------------
extern "C" void kernel_launch(void* const* d_in, const int* in_sizes, int n_in,
                              void* d_out, int out_size)
{
    const float* hs    = (const float*)d_in[0];
    const float* mask  = (const float*)d_in[1];
    const float* extra = (const float*)d_in[2];
    const float* Wq = (const float*)d_in[3];  const float* bq = (const float*)d_in[4];
    const float* Wk = (const float*)d_in[5];  const float* bk = (const float*)d_in[6];
    const float* Wv = (const float*)d_in[7];  const float* bv = (const float*)d_in[8];
    const float* Wo = (const float*)d_in[9];  const float* bo = (const float*)d_in[10];
    const float* gamma = (const float*)d_in[11];
    const float* beta  = (const float*)d_in[12];
    float* out = (float*)d_out;

    // 1) QKV projections
    dim3 g1(48, 32);
    qkv_gemm<<<g1, 256>>>(hs, Wq, bq, Wk, bk, Wv, bv);

    // 2) attention (needs 66560 B dynamic smem > 48 KB default)
    const int smem = 4 * 64 * PAD * (int)sizeof(float);   // 66560
    cudaFuncSetAttribute(attn_kernel, cudaFuncAttributeMaxDynamicSharedMemorySize, smem);
    dim3 g2(SS / 64, BH);
    attn_kernel<<<g2, 256, smem>>>(extra, mask);

    // 3) output projection
    dim3 g3(16, 32);
    proj_gemm<<<g3, 256>>>(Wo, bo);

    // 4) residual + LayerNorm
    ln_kernel<<<MROWS, 256>>>(hs, gamma, beta, out);
}

// round 4
// speedup vs baseline: 2.7881x; 2.7881x over previous
#include <cuda_runtime.h>
#include <math.h>
#include <stdint.h>

#define BB 2
#define SS 2048
#define DD 1024
#define HH 16
#define HD 64
#define BH (BB*HH)        // 32
#define MROWS (BB*SS)     // 4096

// ---------------- scratch (device globals; no allocations allowed) ----------
__device__ float g_q[BH * SS * HD];     // [bh][s][d]
__device__ float g_k[BH * SS * HD];
__device__ float g_v[BH * SS * HD];
__device__ float g_ctx[MROWS * DD];     // [b*s][h*64+d]
__device__ float g_proj[MROWS * DD];

// ---------------- tf32 helpers ----------------------------------------------
__device__ __forceinline__ uint32_t f2tf(float x) {
    uint32_t r;
    asm("cvt.rna.tf32.f32 %0, %1;" : "=r"(r) : "f"(x));
    return r;
}

__device__ __forceinline__ void mma_tf32(float* c,
                                         uint32_t a0, uint32_t a1, uint32_t a2, uint32_t a3,
                                         uint32_t b0, uint32_t b1)
{
    asm volatile(
        "mma.sync.aligned.m16n8k8.row.col.f32.tf32.tf32.f32 "
        "{%0,%1,%2,%3}, {%4,%5,%6,%7}, {%8,%9}, {%0,%1,%2,%3};"
        : "+f"(c[0]), "+f"(c[1]), "+f"(c[2]), "+f"(c[3])
        : "r"(a0), "r"(a1), "r"(a2), "r"(a3), "r"(b0), "r"(b1));
}

// =============================================================================
// kernel 1: fused QKV projection  (tf32 tensor cores)
// C[m,n] = sum_k hs[m,k]*W[n,k] (+bias)(*scale), scatter to [bh][s][d].
// 256 thr = 8 warps (4m x 2n). BM=128, BN=64, BK=32. Warp tile 32x32.
// =============================================================================
__global__ __launch_bounds__(256) void qkv_tc(
    const float* __restrict__ hs,
    const float* __restrict__ Wq, const float* __restrict__ bq,
    const float* __restrict__ Wk, const float* __restrict__ bk,
    const float* __restrict__ Wv, const float* __restrict__ bv)
{
    __shared__ float As[128 * 36];
    __shared__ float Bs[64 * 36];

    const int m0    = blockIdx.y * 128;
    const int nblk  = blockIdx.x;
    const int which = nblk >> 4;
    const int n0    = (nblk & 15) * 64;

    const float* Wp  = (which == 0) ? Wq : (which == 1 ? Wk : Wv);
    const float* bp  = (which == 0) ? bq : (which == 1 ? bk : bv);
    float*       dst = (which == 0) ? g_q : (which == 1 ? g_k : g_v);
    const float scale = (which == 0) ? 0.125f : 1.0f;

    const int tid = threadIdx.x;
    const int w = tid >> 5, lane = tid & 31;
    const int wm = w >> 1, wn = w & 1;
    const int gid = lane >> 2, tg = lane & 3;

    float acc[2][4][4];
#pragma unroll
    for (int t = 0; t < 2; t++)
#pragma unroll
        for (int j = 0; j < 4; j++)
#pragma unroll
            for (int e = 0; e < 4; e++) acc[t][j][e] = 0.f;

    for (int k0 = 0; k0 < DD; k0 += 32) {
#pragma unroll
        for (int i = 0; i < 4; i++) {                 // A tile 128x32
            int idx = tid + i * 256;
            int r = idx >> 3, c4 = (idx & 7) * 4;
            float4 v = *(const float4*)&hs[(size_t)(m0 + r) * DD + k0 + c4];
            float* d = &As[r * 36 + c4];
            d[0] = __uint_as_float(f2tf(v.x)); d[1] = __uint_as_float(f2tf(v.y));
            d[2] = __uint_as_float(f2tf(v.z)); d[3] = __uint_as_float(f2tf(v.w));
        }
#pragma unroll
        for (int i = 0; i < 2; i++) {                 // B tile 64x32
            int idx = tid + i * 256;
            int r = idx >> 3, c4 = (idx & 7) * 4;
            float4 v = *(const float4*)&Wp[(size_t)(n0 + r) * DD + k0 + c4];
            float* d = &Bs[r * 36 + c4];
            d[0] = __uint_as_float(f2tf(v.x)); d[1] = __uint_as_float(f2tf(v.y));
            d[2] = __uint_as_float(f2tf(v.z)); d[3] = __uint_as_float(f2tf(v.w));
        }
        __syncthreads();

#pragma unroll
        for (int kk = 0; kk < 4; kk++) {
            uint32_t a[2][4];
#pragma unroll
            for (int t = 0; t < 2; t++) {
                const float* ab = &As[(wm * 32 + t * 16 + gid) * 36 + kk * 8 + tg];
                a[t][0] = __float_as_uint(ab[0]);
                a[t][1] = __float_as_uint(ab[8 * 36]);
                a[t][2] = __float_as_uint(ab[4]);
                a[t][3] = __float_as_uint(ab[8 * 36 + 4]);
            }
#pragma unroll
            for (int j = 0; j < 4; j++) {
                const float* bbp = &Bs[(wn * 32 + j * 8 + gid) * 36 + kk * 8 + tg];
                uint32_t b0 = __float_as_uint(bbp[0]);
                uint32_t b1 = __float_as_uint(bbp[4]);
#pragma unroll
                for (int t = 0; t < 2; t++)
                    mma_tf32(acc[t][j], a[t][0], a[t][1], a[t][2], a[t][3], b0, b1);
            }
        }
        __syncthreads();
    }

    // epilogue: +bias, *scale, scatter to [bh][s][d]
#pragma unroll
    for (int t = 0; t < 2; t++) {
#pragma unroll
        for (int j = 0; j < 4; j++) {
            int col = n0 + wn * 32 + j * 8 + 2 * tg;
            int h = col >> 6, d = col & 63;
            float b0v = bp[col], b1v = bp[col + 1];
#pragma unroll
            for (int rr = 0; rr < 2; rr++) {
                int m = m0 + wm * 32 + t * 16 + gid + rr * 8;
                int b = m >> 11, s = m & 2047;
                float2 o;
                o.x = (acc[t][j][rr * 2 + 0] + b0v) * scale;
                o.y = (acc[t][j][rr * 2 + 1] + b1v) * scale;
                *(float2*)&dst[(((size_t)(b * HH + h)) * SS + s) * HD + d] = o;
            }
        }
    }
}

// =============================================================================
// kernel 2: flash attention, tf32 tensor cores
// 128 thr = 4 warps. Block: 64 q-rows, loop over 32 k-tiles of 64.
// Warp tile: 16q x 64kcol. extra+mask folded into mma accumulator init.
// =============================================================================
__global__ __launch_bounds__(128) void attn_tc(const float* __restrict__ extra,
                                               const float* __restrict__ mask)
{
    extern __shared__ float sm[];
    float* Qs = sm;                  // [64][68]
    float* Ks = Qs + 64 * 68;        // [64][68]
    float* Vs = Ks + 64 * 68;        // [64][72]  (pad 72 -> conflict-free B-frag gather)
    float* Ps = Vs + 64 * 72;        // [64][68]  warp-private rows

    const int bh = blockIdx.y, b = bh >> 4, h = bh & 15;
    const int q0 = blockIdx.x * 64;
    const int tid = threadIdx.x;
    const int w = tid >> 5, lane = tid & 31;
    const int gid = lane >> 2, tg = lane & 3;
    const int qr = w * 16 + gid;     // this thread's local q row (frag rows qr, qr+8)

    // load Q tile (cvt to tf32)
#pragma unroll
    for (int i = 0; i < 8; i++) {
        int idx = tid + i * 128;
        int r = idx >> 4, c4 = (idx & 15) * 4;
        float4 v = *(const float4*)&g_q[((size_t)bh * SS + q0 + r) * HD + c4];
        float* d = &Qs[r * 68 + c4];
        d[0] = __uint_as_float(f2tf(v.x)); d[1] = __uint_as_float(f2tf(v.y));
        d[2] = __uint_as_float(f2tf(v.z)); d[3] = __uint_as_float(f2tf(v.w));
    }

    float oacc[8][4];
#pragma unroll
    for (int j = 0; j < 8; j++)
#pragma unroll
        for (int e = 0; e < 4; e++) oacc[j][e] = 0.f;
    float mi0 = -1e30f, mi1 = -1e30f, li0 = 0.f, li1 = 0.f;

    const float* erow = extra + ((size_t)bh * SS + q0 + qr) * SS;
    const float* mrow = mask  + ((size_t)b  * SS + q0 + qr) * SS;

    for (int kt = 0; kt < 32; kt++) {
        const int k0 = kt * 64;
        __syncthreads();   // protects Ks/Vs overwrite (1st iter: orders Qs too)

        // load K, V tiles
#pragma unroll
        for (int i = 0; i < 8; i++) {
            int idx = tid + i * 128;
            int r = idx >> 4, c4 = (idx & 15) * 4;
            size_t g = ((size_t)bh * SS + k0 + r) * HD + c4;
            float4 kv = *(const float4*)&g_k[g];
            float* dk = &Ks[r * 68 + c4];
            dk[0] = __uint_as_float(f2tf(kv.x)); dk[1] = __uint_as_float(f2tf(kv.y));
            dk[2] = __uint_as_float(f2tf(kv.z)); dk[3] = __uint_as_float(f2tf(kv.w));
            float4 vv = *(const float4*)&g_v[g];
            float* dv = &Vs[r * 72 + c4];
            dv[0] = __uint_as_float(f2tf(vv.x)); dv[1] = __uint_as_float(f2tf(vv.y));
            dv[2] = __uint_as_float(f2tf(vv.z)); dv[3] = __uint_as_float(f2tf(vv.w));
        }
        __syncthreads();

        // scores accumulator initialized with extra + mask (free add + prefetch)
        float sacc[8][4];
#pragma unroll
        for (int j = 0; j < 8; j++) {
            int c = k0 + j * 8 + 2 * tg;
            float2 e0 = *(const float2*)&erow[c];
            float2 m0 = *(const float2*)&mrow[c];
            float2 e1 = *(const float2*)&erow[8 * SS + c];
            float2 m1 = *(const float2*)&mrow[8 * SS + c];
            sacc[j][0] = e0.x + m0.x; sacc[j][1] = e0.y + m0.y;
            sacc[j][2] = e1.x + m1.x; sacc[j][3] = e1.y + m1.y;
        }

        // S += Q K^T
#pragma unroll
        for (int kk = 0; kk < 8; kk++) {
            const float* qb = &Qs[qr * 68 + kk * 8 + tg];
            uint32_t a0 = __float_as_uint(qb[0]);
            uint32_t a1 = __float_as_uint(qb[8 * 68]);
            uint32_t a2 = __float_as_uint(qb[4]);
            uint32_t a3 = __float_as_uint(qb[8 * 68 + 4]);
#pragma unroll
            for (int j = 0; j < 8; j++) {
                const float* kb = &Ks[(j * 8 + gid) * 68 + kk * 8 + tg];
                mma_tf32(sacc[j], a0, a1, a2, a3,
                         __float_as_uint(kb[0]), __float_as_uint(kb[4]));
            }
        }

        // online softmax (rows qr and qr+8; quad = lanes sharing gid)
        float mx0 = -1e30f, mx1 = -1e30f;
#pragma unroll
        for (int j = 0; j < 8; j++) {
            mx0 = fmaxf(mx0, fmaxf(sacc[j][0], sacc[j][1]));
            mx1 = fmaxf(mx1, fmaxf(sacc[j][2], sacc[j][3]));
        }
#pragma unroll
        for (int off = 1; off < 4; off <<= 1) {
            mx0 = fmaxf(mx0, __shfl_xor_sync(0xffffffffu, mx0, off));
            mx1 = fmaxf(mx1, __shfl_xor_sync(0xffffffffu, mx1, off));
        }
        float mn0 = fmaxf(mi0, mx0), mn1 = fmaxf(mi1, mx1);
        float c0 = __expf(mi0 - mn0), c1 = __expf(mi1 - mn1);
        mi0 = mn0; mi1 = mn1;

        float rs0 = 0.f, rs1 = 0.f;
#pragma unroll
        for (int j = 0; j < 8; j++) {
            float p0 = __expf(sacc[j][0] - mn0);
            float p1 = __expf(sacc[j][1] - mn0);
            float p2 = __expf(sacc[j][2] - mn1);
            float p3 = __expf(sacc[j][3] - mn1);
            rs0 += p0 + p1; rs1 += p2 + p3;
            float2 s01, s23;
            s01.x = __uint_as_float(f2tf(p0)); s01.y = __uint_as_float(f2tf(p1));
            s23.x = __uint_as_float(f2tf(p2)); s23.y = __uint_as_float(f2tf(p3));
            *(float2*)&Ps[qr * 68 + j * 8 + 2 * tg] = s01;
            *(float2*)&Ps[(qr + 8) * 68 + j * 8 + 2 * tg] = s23;
        }
#pragma unroll
        for (int off = 1; off < 4; off <<= 1) {
            rs0 += __shfl_xor_sync(0xffffffffu, rs0, off);
            rs1 += __shfl_xor_sync(0xffffffffu, rs1, off);
        }
        li0 = li0 * c0 + rs0;
        li1 = li1 * c1 + rs1;
#pragma unroll
        for (int j = 0; j < 8; j++) {
            oacc[j][0] *= c0; oacc[j][1] *= c0;
            oacc[j][2] *= c1; oacc[j][3] *= c1;
        }
        __syncwarp();   // Ps rows are warp-private: warp sync suffices

        // O += P V
#pragma unroll
        for (int kk = 0; kk < 8; kk++) {
            const float* pb = &Ps[qr * 68 + kk * 8 + tg];
            uint32_t a0 = __float_as_uint(pb[0]);
            uint32_t a1 = __float_as_uint(pb[8 * 68]);
            uint32_t a2 = __float_as_uint(pb[4]);
            uint32_t a3 = __float_as_uint(pb[8 * 68 + 4]);
#pragma unroll
            for (int j = 0; j < 8; j++) {
                uint32_t b0 = __float_as_uint(Vs[(kk * 8 + tg) * 72 + j * 8 + gid]);
                uint32_t b1 = __float_as_uint(Vs[(kk * 8 + tg + 4) * 72 + j * 8 + gid]);
                mma_tf32(oacc[j], a0, a1, a2, a3, b0, b1);
            }
        }
    }

    // epilogue: normalize, write [b*s][h*64+d]
    float inv0 = 1.f / li0, inv1 = 1.f / li1;
#pragma unroll
    for (int j = 0; j < 8; j++) {
        int d = j * 8 + 2 * tg;
        float2 o0, o1;
        o0.x = oacc[j][0] * inv0; o0.y = oacc[j][1] * inv0;
        o1.x = oacc[j][2] * inv1; o1.y = oacc[j][3] * inv1;
        *(float2*)&g_ctx[((size_t)(b * SS) + q0 + qr) * DD + h * HD + d] = o0;
        *(float2*)&g_ctx[((size_t)(b * SS) + q0 + qr + 8) * DD + h * HD + d] = o1;
    }
}

// =============================================================================
// kernel 3: output projection (tf32 tensor cores), same scheme as qkv_tc
// =============================================================================
__global__ __launch_bounds__(256) void proj_tc(const float* __restrict__ Wo,
                                               const float* __restrict__ bo)
{
    __shared__ float As[128 * 36];
    __shared__ float Bs[64 * 36];

    const int m0 = blockIdx.y * 128;
    const int n0 = blockIdx.x * 64;
    const int tid = threadIdx.x;
    const int w = tid >> 5, lane = tid & 31;
    const int wm = w >> 1, wn = w & 1;
    const int gid = lane >> 2, tg = lane & 3;

    float acc[2][4][4];
#pragma unroll
    for (int t = 0; t < 2; t++)
#pragma unroll
        for (int j = 0; j < 4; j++)
#pragma unroll
            for (int e = 0; e < 4; e++) acc[t][j][e] = 0.f;

    for (int k0 = 0; k0 < DD; k0 += 32) {
#pragma unroll
        for (int i = 0; i < 4; i++) {
            int idx = tid + i * 256;
            int r = idx >> 3, c4 = (idx & 7) * 4;
            float4 v = *(const float4*)&g_ctx[(size_t)(m0 + r) * DD + k0 + c4];
            float* d = &As[r * 36 + c4];
            d[0] = __uint_as_float(f2tf(v.x)); d[1] = __uint_as_float(f2tf(v.y));
            d[2] = __uint_as_float(f2tf(v.z)); d[3] = __uint_as_float(f2tf(v.w));
        }
#pragma unroll
        for (int i = 0; i < 2; i++) {
            int idx = tid + i * 256;
            int r = idx >> 3, c4 = (idx & 7) * 4;
            float4 v = *(const float4*)&Wo[(size_t)(n0 + r) * DD + k0 + c4];
            float* d = &Bs[r * 36 + c4];
            d[0] = __uint_as_float(f2tf(v.x)); d[1] = __uint_as_float(f2tf(v.y));
            d[2] = __uint_as_float(f2tf(v.z)); d[3] = __uint_as_float(f2tf(v.w));
        }
        __syncthreads();

#pragma unroll
        for (int kk = 0; kk < 4; kk++) {
            uint32_t a[2][4];
#pragma unroll
            for (int t = 0; t < 2; t++) {
                const float* ab = &As[(wm * 32 + t * 16 + gid) * 36 + kk * 8 + tg];
                a[t][0] = __float_as_uint(ab[0]);
                a[t][1] = __float_as_uint(ab[8 * 36]);
                a[t][2] = __float_as_uint(ab[4]);
                a[t][3] = __float_as_uint(ab[8 * 36 + 4]);
            }
#pragma unroll
            for (int j = 0; j < 4; j++) {
                const float* bbp = &Bs[(wn * 32 + j * 8 + gid) * 36 + kk * 8 + tg];
                uint32_t b0 = __float_as_uint(bbp[0]);
                uint32_t b1 = __float_as_uint(bbp[4]);
#pragma unroll
                for (int t = 0; t < 2; t++)
                    mma_tf32(acc[t][j], a[t][0], a[t][1], a[t][2], a[t][3], b0, b1);
            }
        }
        __syncthreads();
    }

#pragma unroll
    for (int t = 0; t < 2; t++) {
#pragma unroll
        for (int j = 0; j < 4; j++) {
            int col = n0 + wn * 32 + j * 8 + 2 * tg;
            float b0v = bo[col], b1v = bo[col + 1];
#pragma unroll
            for (int rr = 0; rr < 2; rr++) {
                int m = m0 + wm * 32 + t * 16 + gid + rr * 8;
                float2 o;
                o.x = acc[t][j][rr * 2 + 0] + b0v;
                o.y = acc[t][j][rr * 2 + 1] + b1v;
                *(float2*)&g_proj[(size_t)m * DD + col] = o;
            }
        }
    }
}

// =============================================================================
// kernel 4: residual + LayerNorm (memory-bound, 12us)
// =============================================================================
__global__ void ln_kernel(const float* __restrict__ hs,
                          const float* __restrict__ gamma,
                          const float* __restrict__ beta,
                          float* __restrict__ out)
{
    const int row = blockIdx.x;
    const int tid = threadIdx.x;
    __shared__ float sh_s[8], sh_s2[8];

    float x[4];
    float s = 0.f, s2 = 0.f;
#pragma unroll
    for (int i = 0; i < 4; i++) {
        int c = tid + i * 256;
        float v = hs[(size_t)row * DD + c] + g_proj[(size_t)row * DD + c];
        x[i] = v; s += v; s2 += v * v;
    }
#pragma unroll
    for (int off = 16; off; off >>= 1) {
        s  += __shfl_xor_sync(0xffffffffu, s,  off);
        s2 += __shfl_xor_sync(0xffffffffu, s2, off);
    }
    int w = tid >> 5, ln = tid & 31;
    if (ln == 0) { sh_s[w] = s; sh_s2[w] = s2; }
    __syncthreads();
    if (w == 0) {
        s  = (ln < 8) ? sh_s[ln]  : 0.f;
        s2 = (ln < 8) ? sh_s2[ln] : 0.f;
#pragma unroll
        for (int off = 4; off; off >>= 1) {
            s  += __shfl_xor_sync(0xffffffffu, s,  off);
            s2 += __shfl_xor_sync(0xffffffffu, s2, off);
        }
        if (ln == 0) { sh_s[0] = s; sh_s2[0] = s2; }
    }
    __syncthreads();
    float mu  = sh_s[0] * (1.f / DD);
    float var = sh_s2[0] * (1.f / DD) - mu * mu;
    float inv = rsqrtf(var + 1e-5f);
#pragma unroll
    for (int i = 0; i < 4; i++) {
        int c = tid + i * 256;
        out[(size_t)row * DD + c] = (x[i] - mu) * inv * gamma[c] + beta[c];
    }
}

// ---------------- launch -----------------------------------------------------
extern "C" void kernel_launch(void* const* d_in, const int* in_sizes, int n_in,
                              void* d_out, int out_size)
{
    const float* hs    = (const float*)d_in[0];
    const float* mask  = (const float*)d_in[1];
    const float* extra = (const float*)d_in[2];
    const float* Wq = (const float*)d_in[3];  const float* bq = (const float*)d_in[4];
    const float* Wk = (const float*)d_in[5];  const float* bk = (const float*)d_in[6];
    const float* Wv = (const float*)d_in[7];  const float* bv = (const float*)d_in[8];
    const float* Wo = (const float*)d_in[9];  const float* bo = (const float*)d_in[10];
    const float* gamma = (const float*)d_in[11];
    const float* beta  = (const float*)d_in[12];
    float* out = (float*)d_out;

    // 1) QKV projections (tf32 mma)
    dim3 g1(48, 32);
    qkv_tc<<<g1, 256>>>(hs, Wq, bq, Wk, bk, Wv, bv);

    // 2) flash attention (tf32 mma)  smem = (3*64*68 + 64*72)*4 = 70656 B
    const int smem = (3 * 64 * 68 + 64 * 72) * (int)sizeof(float);
    cudaFuncSetAttribute(attn_tc, cudaFuncAttributeMaxDynamicSharedMemorySize, smem);
    dim3 g2(SS / 64, BH);
    attn_tc<<<g2, 128, smem>>>(extra, mask);

    // 3) output projection (tf32 mma)
    dim3 g3(16, 32);
    proj_tc<<<g3, 256>>>(Wo, bo);

    // 4) residual + LayerNorm
    ln_kernel<<<MROWS, 256>>>(hs, gamma, beta, out);
}